// round 4
// baseline (speedup 1.0000x reference)
#include <cuda_runtime.h>

#define HID   32
#define INDIM 128
#define NMAX  100000
#define EMAX  1600000

// ---------------- static device scratch (no allocations allowed) ----------------
__device__ float         g_deg [NMAX];
__device__ float         g_dinv[NMAX];
__device__ unsigned char g_m0[NMAX], g_m1[NMAX], g_m2[NMAX];
__device__ int           g_list0[NMAX], g_list1[NMAX], g_list2[NMAX];
__device__ int2          g_L1[EMAX], g_L2[EMAX], g_L3[EMAX];
__device__ int           g_c0, g_c1, g_c2, g_cL1, g_cL2, g_cL3;
__device__ int           g_i64;
__device__ float         g_y0[(size_t)NMAX * HID];
__device__ float         g_y1[(size_t)NMAX * HID];
__device__ float         g_y2[(size_t)NMAX * HID];
__device__ float         g_a1[(size_t)NMAX * HID];
__device__ float         g_a2[(size_t)NMAX * HID];
__device__ float         g_a3[2 * HID];

// ---------------- helpers ----------------
__device__ __forceinline__ int load_idx(const void* ei, int i64, size_t pos) {
    return i64 ? (int)((const long long*)ei)[pos] : ((const int*)ei)[pos];
}

// ---------------- K0: init + dtype detection ----------------
__global__ void k_init(const void* ei, int N) {
    int i = blockIdx.x * blockDim.x + threadIdx.x;
    if (i < N) {
        g_deg[i] = 1.0f;            // self-loop contribution to degree
        g_m0[i] = 0; g_m1[i] = 0; g_m2[i] = 0;
    }
    if (i < 2 * HID) g_a3[i] = 0.0f;
    if (i < 2) g_m2[i] = 1;         // nodes 0,1 are in F2 (self-loops)
    if (i == 0) {
        g_c0 = g_c1 = g_c2 = 0;
        g_cL1 = g_cL2 = g_cL3 = 0;
        // int64 vs int32 detection: node ids < 2^31, so if data is int64 the
        // high 32-bit word of every element is 0. 256 random int32 src values
        // all being zero has probability ~1e-1280.
        const unsigned int* w = (const unsigned int*)ei;
        int is64 = 1;
        for (int k = 0; k < 256; k++)
            if (w[2 * k + 1] != 0u) { is64 = 0; break; }
        g_i64 = is64;
    }
}

// ---------------- K1: degree + edges into {0,1} ----------------
__global__ void k_deg_l3(const void* __restrict__ ei, int E) {
    int e = blockIdx.x * blockDim.x + threadIdx.x;
    if (e >= E) return;
    int i64 = g_i64;
    int d = load_idx(ei, i64, (size_t)E + e);
    atomicAdd(&g_deg[d], 1.0f);
    if (d < 2) {
        int s = load_idx(ei, i64, (size_t)e);
        g_m2[s] = 1;
        int p = atomicAdd(&g_cL3, 1);
        if (p < EMAX) g_L3[p] = make_int2(s, d);
    }
}

// ---------------- K2: dinv, list2, m1=m2, zero a2 rows ----------------
__global__ void k_node2(int N) {
    int n = blockIdx.x * blockDim.x + threadIdx.x;
    if (n >= N) return;
    g_dinv[n] = rsqrtf(g_deg[n]);
    unsigned char m = g_m2[n];
    g_m1[n] = m;
    if (m) {
        int p = atomicAdd(&g_c2, 1);
        g_list2[p] = n;
        #pragma unroll
        for (int j = 0; j < HID; j++) g_a2[(size_t)n * HID + j] = 0.0f;
    }
}

// ---------------- K3: edges into F2 ----------------
__global__ void k_scan2(const void* __restrict__ ei, int E) {
    int e = blockIdx.x * blockDim.x + threadIdx.x;
    if (e >= E) return;
    int i64 = g_i64;
    int d = load_idx(ei, i64, (size_t)E + e);
    if (g_m2[d]) {
        int s = load_idx(ei, i64, (size_t)e);
        g_m1[s] = 1;
        int p = atomicAdd(&g_cL2, 1);
        if (p < EMAX) g_L2[p] = make_int2(s, d);
    }
}

// ---------------- K4: list1, m0=m1, zero a1 rows ----------------
__global__ void k_node1(int N) {
    int n = blockIdx.x * blockDim.x + threadIdx.x;
    if (n >= N) return;
    unsigned char m = g_m1[n];
    g_m0[n] = m;
    if (m) {
        int p = atomicAdd(&g_c1, 1);
        g_list1[p] = n;
        #pragma unroll
        for (int j = 0; j < HID; j++) g_a1[(size_t)n * HID + j] = 0.0f;
    }
}

// ---------------- K5: edges into F1 ----------------
__global__ void k_scan1(const void* __restrict__ ei, int E) {
    int e = blockIdx.x * blockDim.x + threadIdx.x;
    if (e >= E) return;
    int i64 = g_i64;
    int d = load_idx(ei, i64, (size_t)E + e);
    if (g_m1[d]) {
        int s = load_idx(ei, i64, (size_t)e);
        g_m0[s] = 1;
        int p = atomicAdd(&g_cL1, 1);
        if (p < EMAX) g_L1[p] = make_int2(s, d);
    }
}

// ---------------- K6: list0 ----------------
__global__ void k_node0(int N) {
    int n = blockIdx.x * blockDim.x + threadIdx.x;
    if (n >= N) return;
    if (g_m0[n]) {
        int p = atomicAdd(&g_c0, 1);
        g_list0[p] = n;
    }
}

// ---------------- K7: y0 = x @ W1 at F0 nodes (warp per node) ----------------
__global__ void __launch_bounds__(256) k_y0(const float* __restrict__ x,
                                            const float* __restrict__ W1) {
    int wid  = (blockIdx.x * blockDim.x + threadIdx.x) >> 5;
    int lane = threadIdx.x & 31;
    int nw   = (gridDim.x * blockDim.x) >> 5;
    int cnt  = g_c0;
    for (int i = wid; i < cnt; i += nw) {
        int n = g_list0[i];
        const float* xr = x + (size_t)n * INDIM;
        float xv[4];
        #pragma unroll
        for (int t = 0; t < 4; t++) xv[t] = xr[lane + 32 * t];
        float acc = 0.0f;
        #pragma unroll
        for (int k = 0; k < INDIM; k++) {
            float xk = __shfl_sync(0xffffffffu, xv[k >> 5], k & 31);
            acc = fmaf(xk, W1[k * HID + lane], acc);
        }
        g_y0[(size_t)n * HID + lane] = acc;
    }
}

// ---------------- aggregation: acc[dst] += dinv[s]*dinv[d]*Y[src] ----------------
__device__ __forceinline__ void agg_body(const int2* __restrict__ L, int cnt,
                                         const float* __restrict__ Y,
                                         float* __restrict__ A) {
    int wid  = (blockIdx.x * blockDim.x + threadIdx.x) >> 5;
    int lane = threadIdx.x & 31;
    int nw   = (gridDim.x * blockDim.x) >> 5;
    for (int i = wid; i < cnt; i += nw) {
        int2 ed = L[i];
        float w = g_dinv[ed.x] * g_dinv[ed.y];
        atomicAdd(&A[(size_t)ed.y * HID + lane], w * Y[(size_t)ed.x * HID + lane]);
    }
}
__global__ void __launch_bounds__(256) k_agg1() { agg_body(g_L1, g_cL1, g_y0, g_a1); }
__global__ void __launch_bounds__(256) k_agg2() { agg_body(g_L2, g_cL2, g_y1, g_a2); }
__global__ void __launch_bounds__(256) k_agg3() { agg_body(g_L3, g_cL3, g_y2, g_a3); }

// ------- node update: h = relu(acc + dinv^2*y_in + b); y_out = h @ Wn -------
__device__ __forceinline__ void layer_body(const int* __restrict__ list, int cnt,
                                           const float* __restrict__ A,
                                           const float* __restrict__ Yin,
                                           const float* __restrict__ b,
                                           const float* __restrict__ Wn,
                                           float* __restrict__ Yout) {
    int wid  = (blockIdx.x * blockDim.x + threadIdx.x) >> 5;
    int lane = threadIdx.x & 31;
    int nw   = (gridDim.x * blockDim.x) >> 5;
    for (int i = wid; i < cnt; i += nw) {
        int n = list[i];
        float dv = g_dinv[n];
        float h = A[(size_t)n * HID + lane]
                + dv * dv * Yin[(size_t)n * HID + lane] + b[lane];
        h = fmaxf(h, 0.0f);
        float acc = 0.0f;
        #pragma unroll
        for (int k = 0; k < HID; k++)
            acc = fmaf(__shfl_sync(0xffffffffu, h, k), Wn[k * HID + lane], acc);
        Yout[(size_t)n * HID + lane] = acc;
    }
}
__global__ void __launch_bounds__(256) k_layer1(const float* b1, const float* W2) {
    layer_body(g_list1, g_c1, g_a1, g_y0, b1, W2, g_y1);
}
__global__ void __launch_bounds__(256) k_layer2(const float* b2, const float* W3) {
    layer_body(g_list2, g_c2, g_a2, g_y1, b2, W3, g_y2);
}

// ---------------- final: h3 at {0,1}, z=concat, out = z@Wfc + bfc ----------------
__global__ void k_final(const float* __restrict__ b3,
                        const float* __restrict__ Wfc,
                        const float* __restrict__ bfc,
                        float* __restrict__ out) {
    __shared__ float z[2 * HID];
    int t = threadIdx.x;            // 64 threads
    int node = t >> 5, lane = t & 31;
    float dv = g_dinv[node];
    float h = g_a3[node * HID + lane]
            + dv * dv * g_y2[(size_t)node * HID + lane] + b3[lane];
    z[t] = fmaxf(h, 0.0f);
    __syncthreads();
    float acc = bfc[t];
    #pragma unroll
    for (int i = 0; i < 2 * HID; i++)
        acc = fmaf(z[i], Wfc[i * 64 + t], acc);
    out[t] = acc;
}

// ---------------- launcher ----------------
extern "C" void kernel_launch(void* const* d_in, const int* in_sizes, int n_in,
                              void* d_out, int out_size) {
    const float* x   = (const float*)d_in[0];
    const void*  ei  = d_in[1];               // int64 or int32, auto-detected
    const float* W1  = (const float*)d_in[2];
    const float* b1  = (const float*)d_in[3];
    const float* W2  = (const float*)d_in[4];
    const float* b2  = (const float*)d_in[5];
    const float* W3  = (const float*)d_in[6];
    const float* b3  = (const float*)d_in[7];
    const float* Wfc = (const float*)d_in[8];
    const float* bfc = (const float*)d_in[9];
    float* out = (float*)d_out;

    int N = in_sizes[0] / INDIM;
    int E = in_sizes[1] / 2;
    int nb = (N + 255) / 256;
    int eb = (E + 255) / 256;

    k_init  <<<nb, 256>>>(ei, N);
    k_deg_l3<<<eb, 256>>>(ei, E);
    k_node2 <<<nb, 256>>>(N);
    k_scan2 <<<eb, 256>>>(ei, E);
    k_node1 <<<nb, 256>>>(N);
    k_scan1 <<<eb, 256>>>(ei, E);
    k_node0 <<<nb, 256>>>(N);
    k_y0    <<<256, 256>>>(x, W1);
    k_agg1  <<<128, 256>>>();
    k_layer1<<<32, 256>>>(b1, W2);
    k_agg2  <<<32, 256>>>();
    k_layer2<<<4, 256>>>(b2, W3);
    k_agg3  <<<2, 256>>>();
    k_final <<<1, 64>>>(b3, Wfc, bfc, out);
}